// round 1
// baseline (speedup 1.0000x reference)
#include <cuda_runtime.h>
#include <math.h>

#define BB    64
#define LL    200
#define HIDN  256
#define NH    8
#define DHD   256
#define HD    2048
#define MAREA 990      // 200+199+198+197+196
#define FFD   1024
#define ROWS  (BB*LL)  // 12800
#define BHCNT (BB*NH)  // 512

// ---------------- scratch (static device globals; no allocation) ----------------
__device__ float g_Q[(size_t)BHCNT*LL*DHD];        // [B,H,L,D]
__device__ float g_K[(size_t)BHCNT*LL*DHD];
__device__ float g_V[(size_t)BHCNT*LL*DHD];
__device__ float g_Karea[(size_t)BHCNT*MAREA*DHD]; // [B,H,M,D]
__device__ float g_Varea[(size_t)BHCNT*MAREA*DHD];
__device__ float g_P[(size_t)BHCNT*LL*MAREA];      // [B,H,L,M]
__device__ float g_concat[(size_t)ROWS*HD];        // [B,L,HD]
__device__ float g_attn1[(size_t)ROWS*HIDN];
__device__ float g_attn2[(size_t)ROWS*HIDN];
__device__ float g_ff[(size_t)ROWS*FFD];
__device__ float g_tmp[(size_t)ROWS*HIDN];

// ---------------- generic tiled SGEMM ----------------
// C[z] = scale * A[z] @ B[z](^T) + bias, optional relu, output-layout modes.
// MODE 0: C[z*sC + r*Nr + c]
// MODE 1: rows are b*L+l, cols are h*256+d -> C[((b*NH+h)*LL+l)*DHD+d]   (QKV split)
// MODE 2: z = b*NH+h, C[(b*LL+r)*HD + h*DHD + c]                         (head concat)
template<bool TRANSB, int MODE, bool RELU>
__global__ __launch_bounds__(256) void sgemm_k(
    const float* __restrict__ A, const float* __restrict__ Bm,
    const float* __restrict__ bias, float* __restrict__ C,
    int Mr, int Nr, int Kr, float scale,
    size_t sA, size_t sB, size_t sC)
{
    const int BM = 64, BN = 64, BK = 16, TM = 4, TN = 4;
    __shared__ float As[BK][BM];
    __shared__ float Bs[BK][BN + 1];

    int z = blockIdx.z;
    A  += (size_t)z * sA;
    Bm += (size_t)z * sB;

    int row0 = blockIdx.y * BM;
    int col0 = blockIdx.x * BN;
    int tid  = threadIdx.x;
    int tx   = tid & 15;
    int ty   = tid >> 4;

    float acc[TM][TN];
#pragma unroll
    for (int i = 0; i < TM; i++)
#pragma unroll
        for (int j = 0; j < TN; j++) acc[i][j] = 0.f;

    for (int k0 = 0; k0 < Kr; k0 += BK) {
        // A tile: 64x16
#pragma unroll
        for (int i = 0; i < 4; i++) {
            int idx = tid + i * 256;
            int r = idx / BK, c = idx % BK;
            int gr = row0 + r, gc = k0 + c;
            As[c][r] = (gr < Mr && gc < Kr) ? A[(size_t)gr * Kr + gc] : 0.f;
        }
        // B tile: 16x64 (or transposed source)
#pragma unroll
        for (int i = 0; i < 4; i++) {
            int idx = tid + i * 256;
            if (!TRANSB) {
                int r = idx / BN, c = idx % BN;
                int gk = k0 + r, gn = col0 + c;
                Bs[r][c] = (gk < Kr && gn < Nr) ? Bm[(size_t)gk * Nr + gn] : 0.f;
            } else {
                int r = idx / BK, c = idx % BK;
                int gn = col0 + r, gk = k0 + c;
                Bs[c][r] = (gn < Nr && gk < Kr) ? Bm[(size_t)gn * Kr + gk] : 0.f;
            }
        }
        __syncthreads();
#pragma unroll
        for (int k = 0; k < BK; k++) {
            float ra[TM], rb[TN];
#pragma unroll
            for (int i = 0; i < TM; i++) ra[i] = As[k][ty * TM + i];
#pragma unroll
            for (int j = 0; j < TN; j++) rb[j] = Bs[k][tx * TN + j];
#pragma unroll
            for (int i = 0; i < TM; i++)
#pragma unroll
                for (int j = 0; j < TN; j++) acc[i][j] += ra[i] * rb[j];
        }
        __syncthreads();
    }

#pragma unroll
    for (int i = 0; i < TM; i++) {
        int gr = row0 + ty * TM + i;
        if (gr >= Mr) continue;
#pragma unroll
        for (int j = 0; j < TN; j++) {
            int gc = col0 + tx * TN + j;
            if (gc >= Nr) continue;
            float v = acc[i][j] * scale;
            if (bias) v += bias[gc];
            if (RELU) v = fmaxf(v, 0.f);
            size_t oidx;
            if (MODE == 0) {
                oidx = (size_t)z * sC + (size_t)gr * Nr + gc;
            } else if (MODE == 1) {
                int b = gr / LL, l = gr % LL;
                int h = gc >> 8, d = gc & 255;
                oidx = (((size_t)b * NH + h) * LL + l) * DHD + d;
            } else { // MODE 2
                int b = z >> 3, h = z & 7;
                oidx = ((size_t)(b * LL + gr)) * HD + (size_t)h * DHD + gc;
            }
            C[oidx] = v;
        }
    }
}

// ---------------- area pooling: K max-pool, V sum-pool over widths 1..5 ----------------
__global__ void area_pool_k(const float* __restrict__ K, const float* __restrict__ V,
                            float* __restrict__ Ka, float* __restrict__ Va)
{
    int d  = threadIdx.x;   // 256
    int m  = blockIdx.x;    // 990
    int bh = blockIdx.y;    // 512
    int w = 1, rem = m, span = LL;
    while (rem >= span) { rem -= span; span--; w++; }
    int start = rem;
    const float* kp = K + ((size_t)bh * LL + start) * DHD + d;
    const float* vp = V + ((size_t)bh * LL + start) * DHD + d;
    float mx = kp[0];
    float sm = vp[0];
    for (int j = 1; j < w; j++) {
        mx = fmaxf(mx, kp[(size_t)j * DHD]);
        sm += vp[(size_t)j * DHD];
    }
    Ka[((size_t)bh * MAREA + m) * DHD + d] = mx;
    Va[((size_t)bh * MAREA + m) * DHD + d] = sm;
}

// ---------------- row softmax over M=990 ----------------
__global__ void softmax_k(float* __restrict__ P)
{
    size_t row = blockIdx.x;
    float* p = P + row * MAREA;
    int t = threadIdx.x;
    float vals[4];
    float mx = -1e30f;
#pragma unroll
    for (int i = 0; i < 4; i++) {
        int idx = t + i * 256;
        vals[i] = (idx < MAREA) ? p[idx] : -1e30f;
        mx = fmaxf(mx, vals[i]);
    }
    __shared__ float sred[8];
#pragma unroll
    for (int o = 16; o > 0; o >>= 1) mx = fmaxf(mx, __shfl_xor_sync(0xffffffffu, mx, o));
    if ((t & 31) == 0) sred[t >> 5] = mx;
    __syncthreads();
    if (t < 32) {
        float v = (t < 8) ? sred[t] : -1e30f;
#pragma unroll
        for (int o = 4; o > 0; o >>= 1) v = fmaxf(v, __shfl_xor_sync(0xffffffffu, v, o));
        if (t == 0) sred[0] = v;
    }
    __syncthreads();
    float bm = sred[0];
    __syncthreads();
    float s = 0.f;
#pragma unroll
    for (int i = 0; i < 4; i++) {
        int idx = t + i * 256;
        vals[i] = (idx < MAREA) ? __expf(vals[i] - bm) : 0.f;
        s += vals[i];
    }
#pragma unroll
    for (int o = 16; o > 0; o >>= 1) s += __shfl_xor_sync(0xffffffffu, s, o);
    if ((t & 31) == 0) sred[t >> 5] = s;
    __syncthreads();
    if (t < 32) {
        float v = (t < 8) ? sred[t] : 0.f;
#pragma unroll
        for (int o = 4; o > 0; o >>= 1) v += __shfl_xor_sync(0xffffffffu, v, o);
        if (t == 0) sred[0] = v;
    }
    __syncthreads();
    float inv = 1.f / sred[0];
#pragma unroll
    for (int i = 0; i < 4; i++) {
        int idx = t + i * 256;
        if (idx < MAREA) p[idx] = vals[i] * inv;
    }
}

// ---------------- fused residual add + layernorm (row = 256 = blockDim) ----------------
__global__ void resid_ln_k(const float* __restrict__ a, const float* __restrict__ b,
                           float* __restrict__ o)
{
    int row = blockIdx.x;
    int t   = threadIdx.x;
    size_t idx = (size_t)row * HIDN + t;
    float x = a[idx] + b[idx];
    float s = x, ss = x * x;
    __shared__ float s1[8], s2[8];
#pragma unroll
    for (int off = 16; off > 0; off >>= 1) {
        s  += __shfl_xor_sync(0xffffffffu, s, off);
        ss += __shfl_xor_sync(0xffffffffu, ss, off);
    }
    if ((t & 31) == 0) { s1[t >> 5] = s; s2[t >> 5] = ss; }
    __syncthreads();
    if (t < 32) {
        float u  = (t < 8) ? s1[t] : 0.f;
        float uu = (t < 8) ? s2[t] : 0.f;
#pragma unroll
        for (int off = 4; off > 0; off >>= 1) {
            u  += __shfl_xor_sync(0xffffffffu, u, off);
            uu += __shfl_xor_sync(0xffffffffu, uu, off);
        }
        if (t == 0) { s1[0] = u; s2[0] = uu; }
    }
    __syncthreads();
    float mean = s1[0] * (1.f / HIDN);
    float var  = s2[0] * (1.f / HIDN) - mean * mean;
    o[idx] = (x - mean) * rsqrtf(var + 1e-5f);
}

// ---------------- host orchestration ----------------
static inline int cdiv(int a, int b) { return (a + b - 1) / b; }

static void run_attention(const float* qsrc, const float* Wq, const float* bq,
                          const float* Wo, const float* bo,
                          float* pQ, float* pKa, float* pVa, float* pP,
                          float* pConcat, float* pOut)
{
    // Q projection + head split
    sgemm_k<false, 1, false><<<dim3(cdiv(HD, 64), cdiv(ROWS, 64), 1), 256>>>(
        qsrc, Wq, bq, pQ, ROWS, HD, HIDN, 1.f, 0, 0, 0);
    // logits = Q @ Karea^T * 1/sqrt(Dh), batched over 512 (b,h)
    sgemm_k<true, 0, false><<<dim3(cdiv(MAREA, 64), cdiv(LL, 64), BHCNT), 256>>>(
        pQ, pKa, nullptr, pP, LL, MAREA, DHD, 0.0625f,
        (size_t)LL * DHD, (size_t)MAREA * DHD, (size_t)LL * MAREA);
    // softmax rows
    softmax_k<<<(unsigned)((size_t)BHCNT * LL), 256>>>(pP);
    // out = P @ Varea, concat heads -> [B,L,HD]
    sgemm_k<false, 2, false><<<dim3(cdiv(DHD, 64), cdiv(LL, 64), BHCNT), 256>>>(
        pP, pVa, nullptr, pConcat, LL, DHD, MAREA, 1.f,
        (size_t)LL * MAREA, (size_t)MAREA * DHD, 0);
    // output projection
    sgemm_k<false, 0, false><<<dim3(cdiv(HIDN, 64), cdiv(ROWS, 64), 1), 256>>>(
        pConcat, Wo, bo, pOut, ROWS, HIDN, HD, 1.f, 0, 0, 0);
}

extern "C" void kernel_launch(void* const* d_in, const int* in_sizes, int n_in,
                              void* d_out, int out_size)
{
    const float* hidden = (const float*)d_in[1];
    const float* Wq = (const float*)d_in[2];
    const float* bq = (const float*)d_in[3];
    const float* Wk = (const float*)d_in[4];
    const float* bk = (const float*)d_in[5];
    const float* Wv = (const float*)d_in[6];
    const float* bv = (const float*)d_in[7];
    const float* Wo = (const float*)d_in[8];
    const float* bo = (const float*)d_in[9];
    const float* W1 = (const float*)d_in[10];
    const float* b1 = (const float*)d_in[11];
    const float* W2 = (const float*)d_in[12];
    const float* b2 = (const float*)d_in[13];
    float* out = (float*)d_out;

    float *pQ, *pK, *pV, *pKa, *pVa, *pP, *pConcat, *pA1, *pA2, *pFF, *pTmp;
    cudaGetSymbolAddress((void**)&pQ, g_Q);
    cudaGetSymbolAddress((void**)&pK, g_K);
    cudaGetSymbolAddress((void**)&pV, g_V);
    cudaGetSymbolAddress((void**)&pKa, g_Karea);
    cudaGetSymbolAddress((void**)&pVa, g_Varea);
    cudaGetSymbolAddress((void**)&pP, g_P);
    cudaGetSymbolAddress((void**)&pConcat, g_concat);
    cudaGetSymbolAddress((void**)&pA1, g_attn1);
    cudaGetSymbolAddress((void**)&pA2, g_attn2);
    cudaGetSymbolAddress((void**)&pFF, g_ff);
    cudaGetSymbolAddress((void**)&pTmp, g_tmp);

    // K/V projections + area pooling: shared by both attention passes
    sgemm_k<false, 1, false><<<dim3(cdiv(HD, 64), cdiv(ROWS, 64), 1), 256>>>(
        hidden, Wk, bk, pK, ROWS, HD, HIDN, 1.f, 0, 0, 0);
    sgemm_k<false, 1, false><<<dim3(cdiv(HD, 64), cdiv(ROWS, 64), 1), 256>>>(
        hidden, Wv, bv, pV, ROWS, HD, HIDN, 1.f, 0, 0, 0);
    area_pool_k<<<dim3(MAREA, BHCNT), 256>>>(pK, pV, pKa, pVa);

    // attn1 = LN(mha(hidden) + hidden)
    run_attention(hidden, Wq, bq, Wo, bo, pQ, pKa, pVa, pP, pConcat, pTmp);
    resid_ln_k<<<ROWS, 256>>>(pTmp, hidden, pA1);

    // attn2 = LN(attn1 + mha(attn1; K,V from hidden))
    run_attention(pA1, Wq, bq, Wo, bo, pQ, pKa, pVa, pP, pConcat, pTmp);
    resid_ln_k<<<ROWS, 256>>>(pA1, pTmp, pA2);

    // FFN + final LN
    sgemm_k<false, 0, true><<<dim3(cdiv(FFD, 64), cdiv(ROWS, 64), 1), 256>>>(
        pA2, W1, b1, pFF, ROWS, FFD, HIDN, 1.f, 0, 0, 0);
    sgemm_k<false, 0, false><<<dim3(cdiv(HIDN, 64), cdiv(ROWS, 64), 1), 256>>>(
        pFF, W2, b2, pTmp, ROWS, HIDN, FFD, 1.f, 0, 0, 0);
    resid_ln_k<<<ROWS, 256>>>(pA2, pTmp, out);
}

// round 2
// speedup vs baseline: 3.2529x; 3.2529x over previous
#include <cuda_runtime.h>
#include <math.h>

#define BB    64
#define LL    200
#define HIDN  256
#define NH    8
#define DHD   256
#define HD    2048
#define MAREA 990      // 200+199+198+197+196
#define MPAD  992      // padded memory axis (mult of 8 and 4)
#define FFD   1024
#define ROWS  (BB*LL)  // 12800
#define BHCNT (BB*NH)  // 512

// ---------------- scratch (static device globals; no allocation) ----------------
__device__ float g_Q[(size_t)BHCNT*LL*DHD];         // [B,H,L,D]
__device__ float g_K[(size_t)BHCNT*LL*DHD];
__device__ float g_V[(size_t)BHCNT*LL*DHD];
__device__ float g_Karea[(size_t)BHCNT*MPAD*DHD];   // [B,H,Mpad,D], rows >=990 zeroed
__device__ float g_Varea[(size_t)BHCNT*MPAD*DHD];
__device__ float g_P[(size_t)BHCNT*LL*MPAD];        // [B,H,L,Mpad]
__device__ float g_concat[(size_t)ROWS*HD];         // [B,L,HD]
__device__ float g_attn1[(size_t)ROWS*HIDN];
__device__ float g_attn2[(size_t)ROWS*HIDN];
__device__ float g_ff[(size_t)ROWS*FFD];
__device__ float g_tmp[(size_t)ROWS*HIDN];

// ---------------- 128x128x8 register-blocked SGEMM, 8x8 per thread ----------------
// C[z] = scale * A[z] @ B[z](^T) + bias, optional relu, output-layout modes.
// MODE 0: C[z*sC + r*Nr + c]
// MODE 1: rows are b*L+l, cols are h*256+d -> C[((b*NH+h)*LL+l)*DHD+d]   (QKV split)
// MODE 2: z = b*NH+h, C[(b*LL+r)*HD + h*DHD + c]                         (head concat)
// Requirements: Kr % 8 == 0, Nr % 4 == 0, 16-byte aligned base pointers.
template<bool TRANSB, int MODE, bool RELU>
__global__ __launch_bounds__(256, 2) void sgemm_k(
    const float* __restrict__ A, const float* __restrict__ Bm,
    const float* __restrict__ bias, float* __restrict__ C,
    int Mr, int Nr, int Kr, float scale,
    size_t sA, size_t sB, size_t sC)
{
    __shared__ float As[8][128];
    __shared__ float Bs[8][128];

    const int z = blockIdx.z;
    A  += (size_t)z * sA;
    Bm += (size_t)z * sB;

    const int row0 = blockIdx.y * 128;
    const int col0 = blockIdx.x * 128;
    const int tid  = threadIdx.x;
    const int tx   = tid & 15;   // 0..15 -> output cols
    const int ty   = tid >> 4;   // 0..15 -> output rows

    // global-load indexing: one float4 per thread per tile
    const int ar  = tid & 127;          // A row within tile (warp = 32 consecutive rows, same k)
    const int ak  = (tid >> 7) * 4;     // A k-offset (0 or 4)
    const int bkr = tid >> 5;           // B k-row (non-trans), 0..7
    const int bn  = (tid & 31) * 4;     // B col (non-trans)
    const int br  = tid & 127;          // B row (trans) = output col
    const int bk2 = (tid >> 7) * 4;     // B k-offset (trans)

    float4 pa, pb;

    auto loadA = [&](int k0) {
        int gr = row0 + ar;
        if (gr < Mr) pa = *(const float4*)&A[(size_t)gr * Kr + (k0 + ak)];
        else         pa = make_float4(0.f, 0.f, 0.f, 0.f);
    };
    auto loadB = [&](int k0) {
        if (!TRANSB) {
            int gn = col0 + bn;
            if (gn < Nr) pb = *(const float4*)&Bm[(size_t)(k0 + bkr) * Nr + gn];
            else         pb = make_float4(0.f, 0.f, 0.f, 0.f);
        } else {
            int gn = col0 + br;
            if (gn < Nr) pb = *(const float4*)&Bm[(size_t)gn * Kr + (k0 + bk2)];
            else         pb = make_float4(0.f, 0.f, 0.f, 0.f);
        }
    };

    float acc[8][8];
#pragma unroll
    for (int i = 0; i < 8; i++)
#pragma unroll
        for (int j = 0; j < 8; j++) acc[i][j] = 0.f;

    loadA(0);
    loadB(0);

    for (int k0 = 0; k0 < Kr; k0 += 8) {
        __syncthreads();
        // commit prefetched tile to smem (A transposed to [k][row])
        As[ak + 0][ar] = pa.x;
        As[ak + 1][ar] = pa.y;
        As[ak + 2][ar] = pa.z;
        As[ak + 3][ar] = pa.w;
        if (!TRANSB) {
            *(float4*)&Bs[bkr][bn] = pb;
        } else {
            Bs[bk2 + 0][br] = pb.x;
            Bs[bk2 + 1][br] = pb.y;
            Bs[bk2 + 2][br] = pb.z;
            Bs[bk2 + 3][br] = pb.w;
        }
        __syncthreads();

        if (k0 + 8 < Kr) { loadA(k0 + 8); loadB(k0 + 8); }

#pragma unroll
        for (int k = 0; k < 8; k++) {
            float4 a0 = *(const float4*)&As[k][ty * 4];
            float4 a1 = *(const float4*)&As[k][ty * 4 + 64];
            float4 b0 = *(const float4*)&Bs[k][tx * 4];
            float4 b1 = *(const float4*)&Bs[k][tx * 4 + 64];
            float av[8] = {a0.x, a0.y, a0.z, a0.w, a1.x, a1.y, a1.z, a1.w};
            float bv[8] = {b0.x, b0.y, b0.z, b0.w, b1.x, b1.y, b1.z, b1.w};
#pragma unroll
            for (int i = 0; i < 8; i++)
#pragma unroll
                for (int j = 0; j < 8; j++) acc[i][j] += av[i] * bv[j];
        }
    }

    // ---- epilogue: float4 stores with layout remap ----
#pragma unroll
    for (int ih = 0; ih < 2; ih++) {
#pragma unroll
        for (int i = 0; i < 4; i++) {
            int gr = row0 + ih * 64 + ty * 4 + i;
            if (gr >= Mr) continue;
#pragma unroll
            for (int jh = 0; jh < 2; jh++) {
                int gc = col0 + jh * 64 + tx * 4;
                if (gc >= Nr) continue;   // Nr % 4 == 0 -> whole float4 in/out
                float4 v;
                v.x = acc[ih * 4 + i][jh * 4 + 0] * scale;
                v.y = acc[ih * 4 + i][jh * 4 + 1] * scale;
                v.z = acc[ih * 4 + i][jh * 4 + 2] * scale;
                v.w = acc[ih * 4 + i][jh * 4 + 3] * scale;
                if (bias) {
                    float4 bb = *(const float4*)&bias[gc];
                    v.x += bb.x; v.y += bb.y; v.z += bb.z; v.w += bb.w;
                }
                if (RELU) {
                    v.x = fmaxf(v.x, 0.f); v.y = fmaxf(v.y, 0.f);
                    v.z = fmaxf(v.z, 0.f); v.w = fmaxf(v.w, 0.f);
                }
                size_t o;
                if (MODE == 0) {
                    o = (size_t)z * sC + (size_t)gr * Nr + gc;
                } else if (MODE == 1) {
                    int b = gr / LL, l = gr - (gr / LL) * LL;
                    int h = gc >> 8, d = gc & 255;
                    o = (((size_t)b * NH + h) * LL + l) * DHD + d;
                } else {
                    int b = z >> 3, h = z & 7;
                    o = ((size_t)(b * LL + gr)) * HD + (size_t)h * DHD + gc;
                }
                *(float4*)&C[o] = v;
            }
        }
    }
}

// ---------------- area pooling: K max-pool, V sum-pool over widths 1..5 ----------------
// Writes padded rows [MAREA, MPAD) as zeros so downstream GEMMs need no guards.
__global__ void area_pool_k(const float* __restrict__ K, const float* __restrict__ V,
                            float* __restrict__ Ka, float* __restrict__ Va)
{
    int d  = threadIdx.x;   // 256
    int m  = blockIdx.x;    // MPAD
    int bh = blockIdx.y;    // 512
    size_t oidx = ((size_t)bh * MPAD + m) * DHD + d;
    if (m >= MAREA) { Ka[oidx] = 0.f; Va[oidx] = 0.f; return; }
    int w = 1, rem = m, span = LL;
    while (rem >= span) { rem -= span; span--; w++; }
    int start = rem;
    const float* kp = K + ((size_t)bh * LL + start) * DHD + d;
    const float* vp = V + ((size_t)bh * LL + start) * DHD + d;
    float mx = kp[0];
    float sm = vp[0];
    for (int j = 1; j < w; j++) {
        mx = fmaxf(mx, kp[(size_t)j * DHD]);
        sm += vp[(size_t)j * DHD];
    }
    Ka[oidx] = mx;
    Va[oidx] = sm;
}

// ---------------- row softmax over M=990 (stride MPAD) ----------------
__global__ void softmax_k(float* __restrict__ P)
{
    size_t row = blockIdx.x;
    float* p = P + row * MPAD;
    int t = threadIdx.x;
    float vals[4];
    float mx = -1e30f;
#pragma unroll
    for (int i = 0; i < 4; i++) {
        int idx = t + i * 256;
        vals[i] = (idx < MAREA) ? p[idx] : -1e30f;
        mx = fmaxf(mx, vals[i]);
    }
    __shared__ float sred[8];
#pragma unroll
    for (int o = 16; o > 0; o >>= 1) mx = fmaxf(mx, __shfl_xor_sync(0xffffffffu, mx, o));
    if ((t & 31) == 0) sred[t >> 5] = mx;
    __syncthreads();
    if (t < 32) {
        float v = (t < 8) ? sred[t] : -1e30f;
#pragma unroll
        for (int o = 4; o > 0; o >>= 1) v = fmaxf(v, __shfl_xor_sync(0xffffffffu, v, o));
        if (t == 0) sred[0] = v;
    }
    __syncthreads();
    float bm = sred[0];
    __syncthreads();
    float s = 0.f;
#pragma unroll
    for (int i = 0; i < 4; i++) {
        int idx = t + i * 256;
        vals[i] = (idx < MAREA) ? __expf(vals[i] - bm) : 0.f;
        s += vals[i];
    }
#pragma unroll
    for (int o = 16; o > 0; o >>= 1) s += __shfl_xor_sync(0xffffffffu, s, o);
    if ((t & 31) == 0) sred[t >> 5] = s;
    __syncthreads();
    if (t < 32) {
        float v = (t < 8) ? sred[t] : 0.f;
#pragma unroll
        for (int o = 4; o > 0; o >>= 1) v += __shfl_xor_sync(0xffffffffu, v, o);
        if (t == 0) sred[0] = v;
    }
    __syncthreads();
    float inv = 1.f / sred[0];
#pragma unroll
    for (int i = 0; i < 4; i++) {
        int idx = t + i * 256;
        if (idx < MAREA) p[idx] = vals[i] * inv;
        else if (idx < MPAD) p[idx] = 0.f;
    }
}

// ---------------- fused residual add + layernorm (row = 256 = blockDim) ----------------
__global__ void resid_ln_k(const float* __restrict__ a, const float* __restrict__ b,
                           float* __restrict__ o)
{
    int row = blockIdx.x;
    int t   = threadIdx.x;
    size_t idx = (size_t)row * HIDN + t;
    float x = a[idx] + b[idx];
    float s = x, ss = x * x;
    __shared__ float s1[8], s2[8];
#pragma unroll
    for (int off = 16; off > 0; off >>= 1) {
        s  += __shfl_xor_sync(0xffffffffu, s, off);
        ss += __shfl_xor_sync(0xffffffffu, ss, off);
    }
    if ((t & 31) == 0) { s1[t >> 5] = s; s2[t >> 5] = ss; }
    __syncthreads();
    if (t < 32) {
        float u  = (t < 8) ? s1[t] : 0.f;
        float uu = (t < 8) ? s2[t] : 0.f;
#pragma unroll
        for (int off = 4; off > 0; off >>= 1) {
            u  += __shfl_xor_sync(0xffffffffu, u, off);
            uu += __shfl_xor_sync(0xffffffffu, uu, off);
        }
        if (t == 0) { s1[0] = u; s2[0] = uu; }
    }
    __syncthreads();
    float mean = s1[0] * (1.f / HIDN);
    float var  = s2[0] * (1.f / HIDN) - mean * mean;
    o[idx] = (x - mean) * rsqrtf(var + 1e-5f);
}

// ---------------- host orchestration ----------------
static inline int cdiv(int a, int b) { return (a + b - 1) / b; }

static void run_attention(const float* qsrc, const float* Wq, const float* bq,
                          const float* Wo, const float* bo,
                          float* pQ, float* pKa, float* pVa, float* pP,
                          float* pConcat, float* pOut)
{
    // Q projection + head split: [12800,256] @ [256,2048]
    sgemm_k<false, 1, false><<<dim3(HD / 128, ROWS / 128, 1), 256>>>(
        qsrc, Wq, bq, pQ, ROWS, HD, HIDN, 1.f, 0, 0, 0);
    // logits = Q @ Karea^T * 1/16, batched over 512 (b,h). N padded to 992.
    sgemm_k<true, 0, false><<<dim3(cdiv(MPAD, 128), cdiv(LL, 128), BHCNT), 256>>>(
        pQ, pKa, nullptr, pP, LL, MPAD, DHD, 0.0625f,
        (size_t)LL * DHD, (size_t)MPAD * DHD, (size_t)LL * MPAD);
    // softmax rows
    softmax_k<<<(unsigned)((size_t)BHCNT * LL), 256>>>(pP);
    // out = P @ Varea (K padded to 992, pads are exact zeros), concat heads
    sgemm_k<false, 2, false><<<dim3(DHD / 128, cdiv(LL, 128), BHCNT), 256>>>(
        pP, pVa, nullptr, pConcat, LL, DHD, MPAD, 1.f,
        (size_t)LL * MPAD, (size_t)MPAD * DHD, 0);
    // output projection: [12800,2048] @ [2048,256]
    sgemm_k<false, 0, false><<<dim3(HIDN / 128, ROWS / 128, 1), 256>>>(
        pConcat, Wo, bo, pOut, ROWS, HIDN, HD, 1.f, 0, 0, 0);
}

extern "C" void kernel_launch(void* const* d_in, const int* in_sizes, int n_in,
                              void* d_out, int out_size)
{
    const float* hidden = (const float*)d_in[1];
    const float* Wq = (const float*)d_in[2];
    const float* bq = (const float*)d_in[3];
    const float* Wk = (const float*)d_in[4];
    const float* bk = (const float*)d_in[5];
    const float* Wv = (const float*)d_in[6];
    const float* bv = (const float*)d_in[7];
    const float* Wo = (const float*)d_in[8];
    const float* bo = (const float*)d_in[9];
    const float* W1 = (const float*)d_in[10];
    const float* b1 = (const float*)d_in[11];
    const float* W2 = (const float*)d_in[12];
    const float* b2 = (const float*)d_in[13];
    float* out = (float*)d_out;

    float *pQ, *pK, *pV, *pKa, *pVa, *pP, *pConcat, *pA1, *pA2, *pFF, *pTmp;
    cudaGetSymbolAddress((void**)&pQ, g_Q);
    cudaGetSymbolAddress((void**)&pK, g_K);
    cudaGetSymbolAddress((void**)&pV, g_V);
    cudaGetSymbolAddress((void**)&pKa, g_Karea);
    cudaGetSymbolAddress((void**)&pVa, g_Varea);
    cudaGetSymbolAddress((void**)&pP, g_P);
    cudaGetSymbolAddress((void**)&pConcat, g_concat);
    cudaGetSymbolAddress((void**)&pA1, g_attn1);
    cudaGetSymbolAddress((void**)&pA2, g_attn2);
    cudaGetSymbolAddress((void**)&pFF, g_ff);
    cudaGetSymbolAddress((void**)&pTmp, g_tmp);

    // K/V projections + area pooling: shared by both attention passes
    sgemm_k<false, 1, false><<<dim3(HD / 128, ROWS / 128, 1), 256>>>(
        hidden, Wk, bk, pK, ROWS, HD, HIDN, 1.f, 0, 0, 0);
    sgemm_k<false, 1, false><<<dim3(HD / 128, ROWS / 128, 1), 256>>>(
        hidden, Wv, bv, pV, ROWS, HD, HIDN, 1.f, 0, 0, 0);
    area_pool_k<<<dim3(MPAD, BHCNT), 256>>>(pK, pV, pKa, pVa);

    // attn1 = LN(mha(hidden) + hidden)
    run_attention(hidden, Wq, bq, Wo, bo, pQ, pKa, pVa, pP, pConcat, pTmp);
    resid_ln_k<<<ROWS, 256>>>(pTmp, hidden, pA1);

    // attn2 = LN(attn1 + mha(attn1; K,V from hidden))
    run_attention(pA1, Wq, bq, Wo, bo, pQ, pKa, pVa, pP, pConcat, pTmp);
    resid_ln_k<<<ROWS, 256>>>(pA1, pTmp, pA2);

    // FFN + final LN
    sgemm_k<false, 0, true><<<dim3(FFD / 128, ROWS / 128, 1), 256>>>(
        pA2, W1, b1, pFF, ROWS, FFD, HIDN, 1.f, 0, 0, 0);
    sgemm_k<false, 0, false><<<dim3(HIDN / 128, ROWS / 128, 1), 256>>>(
        pFF, W2, b2, pTmp, ROWS, HIDN, FFD, 1.f, 0, 0, 0);
    resid_ln_k<<<ROWS, 256>>>(pA2, pTmp, out);
}

// round 3
// speedup vs baseline: 5.7707x; 1.7740x over previous
#include <cuda_runtime.h>
#include <math.h>

#define BB    64
#define LL    200
#define HIDN  256
#define NH    8
#define DHD   256
#define HD    2048
#define MAREA 990      // 200+199+198+197+196
#define MPAD  992      // padded memory axis (mult of 16)
#define FFD   1024
#define ROWS  (BB*LL)  // 12800
#define BHCNT (BB*NH)  // 512

// ---------------- scratch (static device globals; no allocation) ----------------
__device__ float g_Q[(size_t)BHCNT*LL*DHD];         // [B,H,L,D]
__device__ float g_K[(size_t)BHCNT*LL*DHD];
__device__ float g_V[(size_t)BHCNT*LL*DHD];
__device__ float g_Karea[(size_t)BHCNT*MPAD*DHD];   // [B,H,Mpad,D], rows >=990 zeroed
__device__ float g_Varea[(size_t)BHCNT*MPAD*DHD];
__device__ float g_P[(size_t)BHCNT*LL*MPAD];        // [B,H,L,Mpad]
__device__ float g_concat[(size_t)ROWS*HD];         // [B,L,HD]
__device__ float g_attn1[(size_t)ROWS*HIDN];
__device__ float g_attn2[(size_t)ROWS*HIDN];
__device__ float g_ff[(size_t)ROWS*FFD];
__device__ float g_tmp[(size_t)ROWS*HIDN];

// ---------------- helpers ----------------
__device__ __forceinline__ unsigned f2tf(float f) {
    unsigned u;
    asm("cvt.rna.tf32.f32 %0, %1;" : "=r"(u) : "f"(f));
    return u;
}

__device__ __forceinline__ void mma_tf32(float* c, const unsigned* a, const unsigned* b) {
    asm volatile(
        "mma.sync.aligned.m16n8k8.row.col.f32.tf32.tf32.f32 "
        "{%0,%1,%2,%3}, {%4,%5,%6,%7}, {%8,%9}, {%0,%1,%2,%3};"
        : "+f"(c[0]), "+f"(c[1]), "+f"(c[2]), "+f"(c[3])
        : "r"(a[0]), "r"(a[1]), "r"(a[2]), "r"(a[3]), "r"(b[0]), "r"(b[1]));
}

// ---------------- 128x128x16 tf32 tensor-core GEMM ----------------
// C[z] = scale * A[z] @ B[z](^T) + bias, optional relu, output-layout modes.
// MODE 0: C[z*sC + r*Nr + c]
// MODE 1: rows are b*L+l, cols are h*256+d -> C[((b*NH+h)*LL+l)*DHD+d]   (QKV split)
// MODE 2: z = b*NH+h, C[(b*LL+r)*HD + h*DHD + c]                         (head concat)
// Requirements: Kr % 16 == 0, Nr even, 16-byte aligned base pointers.
#define SSTRIDE 136   // smem row stride in words: 8-word bank skew -> conflict-free frags
template<bool TRANSB, int MODE, bool RELU>
__global__ __launch_bounds__(256) void tgemm_k(
    const float* __restrict__ A, const float* __restrict__ Bm,
    const float* __restrict__ bias, float* __restrict__ C,
    int Mr, int Nr, int Kr, float scale,
    size_t sA, size_t sB, size_t sC)
{
    __shared__ unsigned As[16 * SSTRIDE];
    __shared__ unsigned Bs[16 * SSTRIDE];

    const int z = blockIdx.z;
    A  += (size_t)z * sA;
    Bm += (size_t)z * sB;

    const int row0 = blockIdx.y * 128;
    const int col0 = blockIdx.x * 128;
    const int tid  = threadIdx.x;
    const int lane = tid & 31;
    const int warp = tid >> 5;
    const int wm = (warp & 3) * 32;   // warp tile: 32 rows x 64 cols
    const int wn = (warp >> 2) * 64;

    // ---- gmem load indexing (one float4 pair per thread per K-tile) ----
    const int am  = tid & 127;        // A row in tile
    const int ak  = (tid >> 7) * 4;   // A k-offset: loads k=ak..ak+3 and ak+8..ak+11
    int bK, bN;                        // B indices
    if (!TRANSB) { bK = tid >> 5; bN = (tid & 31) * 4; }   // B[k][n]
    else         { bN = tid & 127; bK = (tid >> 7) * 4; }  // B[n][k]

    float4 pa0, pa1, pb0, pb1;
    const float4 Z4 = make_float4(0.f, 0.f, 0.f, 0.f);

    auto loadA = [&](int k0) {
        int gr = row0 + am;
        if (gr < Mr) {
            const float* ap = &A[(size_t)gr * Kr + k0 + ak];
            pa0 = *(const float4*)ap;
            pa1 = *(const float4*)(ap + 8);
        } else { pa0 = Z4; pa1 = Z4; }
    };
    auto loadB = [&](int k0) {
        if (!TRANSB) {
            int gn = col0 + bN;
            if (gn < Nr) {
                pb0 = *(const float4*)&Bm[(size_t)(k0 + bK) * Nr + gn];
                pb1 = *(const float4*)&Bm[(size_t)(k0 + bK + 8) * Nr + gn];
            } else { pb0 = Z4; pb1 = Z4; }
        } else {
            int gn = col0 + bN;
            if (gn < Nr) {
                const float* bp = &Bm[(size_t)gn * Kr + k0 + bK];
                pb0 = *(const float4*)bp;
                pb1 = *(const float4*)(bp + 8);
            } else { pb0 = Z4; pb1 = Z4; }
        }
    };

    float acc[2][8][4];
#pragma unroll
    for (int i = 0; i < 2; i++)
#pragma unroll
        for (int j = 0; j < 8; j++)
#pragma unroll
            for (int q = 0; q < 4; q++) acc[i][j][q] = 0.f;

    loadA(0);
    loadB(0);

    for (int k0 = 0; k0 < Kr; k0 += 16) {
        __syncthreads();
        // commit prefetched tile to smem as tf32 words
        {
            float av0[4] = {pa0.x, pa0.y, pa0.z, pa0.w};
            float av1[4] = {pa1.x, pa1.y, pa1.z, pa1.w};
#pragma unroll
            for (int i = 0; i < 4; i++) {
                As[(ak + i) * SSTRIDE + am]     = f2tf(av0[i]);
                As[(ak + 8 + i) * SSTRIDE + am] = f2tf(av1[i]);
            }
            if (!TRANSB) {
                uint4 u0 = make_uint4(f2tf(pb0.x), f2tf(pb0.y), f2tf(pb0.z), f2tf(pb0.w));
                uint4 u1 = make_uint4(f2tf(pb1.x), f2tf(pb1.y), f2tf(pb1.z), f2tf(pb1.w));
                *(uint4*)&Bs[bK * SSTRIDE + bN]       = u0;
                *(uint4*)&Bs[(bK + 8) * SSTRIDE + bN] = u1;
            } else {
                float bv0[4] = {pb0.x, pb0.y, pb0.z, pb0.w};
                float bv1[4] = {pb1.x, pb1.y, pb1.z, pb1.w};
#pragma unroll
                for (int i = 0; i < 4; i++) {
                    Bs[(bK + i) * SSTRIDE + bN]     = f2tf(bv0[i]);
                    Bs[(bK + 8 + i) * SSTRIDE + bN] = f2tf(bv1[i]);
                }
            }
        }
        __syncthreads();

        if (k0 + 16 < Kr) { loadA(k0 + 16); loadB(k0 + 16); }

#pragma unroll
        for (int ks = 0; ks < 2; ks++) {
            const int kb = ks * 8;
            const int q  = lane & 3;     // k within 4
            const int p  = lane >> 2;    // row/col group
            unsigned af[2][4];
#pragma unroll
            for (int im = 0; im < 2; im++) {
                int r = wm + im * 16 + p;
                af[im][0] = As[(kb + q) * SSTRIDE + r];
                af[im][1] = As[(kb + q) * SSTRIDE + r + 8];
                af[im][2] = As[(kb + q + 4) * SSTRIDE + r];
                af[im][3] = As[(kb + q + 4) * SSTRIDE + r + 8];
            }
            unsigned bf[8][2];
#pragma unroll
            for (int in = 0; in < 8; in++) {
                int cn = wn + in * 8 + p;
                bf[in][0] = Bs[(kb + q) * SSTRIDE + cn];
                bf[in][1] = Bs[(kb + q + 4) * SSTRIDE + cn];
            }
#pragma unroll
            for (int im = 0; im < 2; im++)
#pragma unroll
                for (int in = 0; in < 8; in++)
                    mma_tf32(acc[im][in], af[im], bf[in]);
        }
    }

    // ---- epilogue: float2 stores with layout remap ----
    const int p = lane >> 2;
    const int q = lane & 3;
#pragma unroll
    for (int im = 0; im < 2; im++) {
#pragma unroll
        for (int half = 0; half < 2; half++) {
            int gr = row0 + wm + im * 16 + p + half * 8;
            if (gr >= Mr) continue;
#pragma unroll
            for (int in = 0; in < 8; in++) {
                int gc = col0 + wn + in * 8 + 2 * q;
                if (gc >= Nr) continue;   // Nr even, gc even -> pair fully in/out
                float2 v;
                v.x = acc[im][in][half * 2 + 0] * scale;
                v.y = acc[im][in][half * 2 + 1] * scale;
                if (bias) {
                    float2 bb = *(const float2*)&bias[gc];
                    v.x += bb.x; v.y += bb.y;
                }
                if (RELU) { v.x = fmaxf(v.x, 0.f); v.y = fmaxf(v.y, 0.f); }
                size_t o;
                if (MODE == 0) {
                    o = (size_t)z * sC + (size_t)gr * Nr + gc;
                } else if (MODE == 1) {
                    int b = gr / LL, l = gr - (gr / LL) * LL;
                    int h = gc >> 8, d = gc & 255;
                    o = (((size_t)b * NH + h) * LL + l) * DHD + d;
                } else {
                    int b = z >> 3, h = z & 7;
                    o = ((size_t)(b * LL + gr)) * HD + (size_t)h * DHD + gc;
                }
                *(float2*)&C[o] = v;
            }
        }
    }
}

// ---------------- area pooling: K max-pool, V sum-pool over widths 1..5 ----------------
__global__ void area_pool_k(const float* __restrict__ K, const float* __restrict__ V,
                            float* __restrict__ Ka, float* __restrict__ Va)
{
    int d  = threadIdx.x;   // 256
    int m  = blockIdx.x;    // MPAD
    int bh = blockIdx.y;    // 512
    size_t oidx = ((size_t)bh * MPAD + m) * DHD + d;
    if (m >= MAREA) { Ka[oidx] = 0.f; Va[oidx] = 0.f; return; }
    int w = 1, rem = m, span = LL;
    while (rem >= span) { rem -= span; span--; w++; }
    int start = rem;
    const float* kp = K + ((size_t)bh * LL + start) * DHD + d;
    const float* vp = V + ((size_t)bh * LL + start) * DHD + d;
    float mx = kp[0];
    float sm = vp[0];
    for (int j = 1; j < w; j++) {
        mx = fmaxf(mx, kp[(size_t)j * DHD]);
        sm += vp[(size_t)j * DHD];
    }
    Ka[oidx] = mx;
    Va[oidx] = sm;
}

// ---------------- row softmax over M=990 (stride MPAD) ----------------
__global__ void softmax_k(float* __restrict__ P)
{
    size_t row = blockIdx.x;
    float* p = P + row * MPAD;
    int t = threadIdx.x;
    float vals[4];
    float mx = -1e30f;
#pragma unroll
    for (int i = 0; i < 4; i++) {
        int idx = t + i * 256;
        vals[i] = (idx < MAREA) ? p[idx] : -1e30f;
        mx = fmaxf(mx, vals[i]);
    }
    __shared__ float sred[8];
#pragma unroll
    for (int o = 16; o > 0; o >>= 1) mx = fmaxf(mx, __shfl_xor_sync(0xffffffffu, mx, o));
    if ((t & 31) == 0) sred[t >> 5] = mx;
    __syncthreads();
    if (t < 32) {
        float v = (t < 8) ? sred[t] : -1e30f;
#pragma unroll
        for (int o = 4; o > 0; o >>= 1) v = fmaxf(v, __shfl_xor_sync(0xffffffffu, v, o));
        if (t == 0) sred[0] = v;
    }
    __syncthreads();
    float bm = sred[0];
    __syncthreads();
    float s = 0.f;
#pragma unroll
    for (int i = 0; i < 4; i++) {
        int idx = t + i * 256;
        vals[i] = (idx < MAREA) ? __expf(vals[i] - bm) : 0.f;
        s += vals[i];
    }
#pragma unroll
    for (int o = 16; o > 0; o >>= 1) s += __shfl_xor_sync(0xffffffffu, s, o);
    if ((t & 31) == 0) sred[t >> 5] = s;
    __syncthreads();
    if (t < 32) {
        float v = (t < 8) ? sred[t] : 0.f;
#pragma unroll
        for (int o = 4; o > 0; o >>= 1) v += __shfl_xor_sync(0xffffffffu, v, o);
        if (t == 0) sred[0] = v;
    }
    __syncthreads();
    float inv = 1.f / sred[0];
#pragma unroll
    for (int i = 0; i < 4; i++) {
        int idx = t + i * 256;
        if (idx < MAREA) p[idx] = vals[i] * inv;
        else if (idx < MPAD) p[idx] = 0.f;
    }
}

// ---------------- fused residual add + layernorm (row = 256 = blockDim) ----------------
__global__ void resid_ln_k(const float* __restrict__ a, const float* __restrict__ b,
                           float* __restrict__ o)
{
    int row = blockIdx.x;
    int t   = threadIdx.x;
    size_t idx = (size_t)row * HIDN + t;
    float x = a[idx] + b[idx];
    float s = x, ss = x * x;
    __shared__ float s1[8], s2[8];
#pragma unroll
    for (int off = 16; off > 0; off >>= 1) {
        s  += __shfl_xor_sync(0xffffffffu, s, off);
        ss += __shfl_xor_sync(0xffffffffu, ss, off);
    }
    if ((t & 31) == 0) { s1[t >> 5] = s; s2[t >> 5] = ss; }
    __syncthreads();
    if (t < 32) {
        float u  = (t < 8) ? s1[t] : 0.f;
        float uu = (t < 8) ? s2[t] : 0.f;
#pragma unroll
        for (int off = 4; off > 0; off >>= 1) {
            u  += __shfl_xor_sync(0xffffffffu, u, off);
            uu += __shfl_xor_sync(0xffffffffu, uu, off);
        }
        if (t == 0) { s1[0] = u; s2[0] = uu; }
    }
    __syncthreads();
    float mean = s1[0] * (1.f / HIDN);
    float var  = s2[0] * (1.f / HIDN) - mean * mean;
    o[idx] = (x - mean) * rsqrtf(var + 1e-5f);
}

// ---------------- host orchestration ----------------
static inline int cdiv(int a, int b) { return (a + b - 1) / b; }

static void run_attention(const float* qsrc, const float* Wq, const float* bq,
                          const float* Wo, const float* bo,
                          float* pQ, float* pKa, float* pVa, float* pP,
                          float* pConcat, float* pOut)
{
    // Q projection + head split: [12800,256] @ [256,2048]
    tgemm_k<false, 1, false><<<dim3(HD / 128, ROWS / 128, 1), 256>>>(
        qsrc, Wq, bq, pQ, ROWS, HD, HIDN, 1.f, 0, 0, 0);
    // logits = Q @ Karea^T * 1/16, batched over 512 (b,h). N padded to 992.
    tgemm_k<true, 0, false><<<dim3(cdiv(MPAD, 128), cdiv(LL, 128), BHCNT), 256>>>(
        pQ, pKa, nullptr, pP, LL, MPAD, DHD, 0.0625f,
        (size_t)LL * DHD, (size_t)MPAD * DHD, (size_t)LL * MPAD);
    // softmax rows
    softmax_k<<<(unsigned)((size_t)BHCNT * LL), 256>>>(pP);
    // out = P @ Varea (K padded to 992, pads are exact zeros), concat heads
    tgemm_k<false, 2, false><<<dim3(DHD / 128, cdiv(LL, 128), BHCNT), 256>>>(
        pP, pVa, nullptr, pConcat, LL, DHD, MPAD, 1.f,
        (size_t)LL * MPAD, (size_t)MPAD * DHD, 0);
    // output projection: [12800,2048] @ [2048,256]
    tgemm_k<false, 0, false><<<dim3(HIDN / 128, ROWS / 128, 1), 256>>>(
        pConcat, Wo, bo, pOut, ROWS, HIDN, HD, 1.f, 0, 0, 0);
}

extern "C" void kernel_launch(void* const* d_in, const int* in_sizes, int n_in,
                              void* d_out, int out_size)
{
    const float* hidden = (const float*)d_in[1];
    const float* Wq = (const float*)d_in[2];
    const float* bq = (const float*)d_in[3];
    const float* Wk = (const float*)d_in[4];
    const float* bk = (const float*)d_in[5];
    const float* Wv = (const float*)d_in[6];
    const float* bv = (const float*)d_in[7];
    const float* Wo = (const float*)d_in[8];
    const float* bo = (const float*)d_in[9];
    const float* W1 = (const float*)d_in[10];
    const float* b1 = (const float*)d_in[11];
    const float* W2 = (const float*)d_in[12];
    const float* b2 = (const float*)d_in[13];
    float* out = (float*)d_out;

    float *pQ, *pK, *pV, *pKa, *pVa, *pP, *pConcat, *pA1, *pA2, *pFF, *pTmp;
    cudaGetSymbolAddress((void**)&pQ, g_Q);
    cudaGetSymbolAddress((void**)&pK, g_K);
    cudaGetSymbolAddress((void**)&pV, g_V);
    cudaGetSymbolAddress((void**)&pKa, g_Karea);
    cudaGetSymbolAddress((void**)&pVa, g_Varea);
    cudaGetSymbolAddress((void**)&pP, g_P);
    cudaGetSymbolAddress((void**)&pConcat, g_concat);
    cudaGetSymbolAddress((void**)&pA1, g_attn1);
    cudaGetSymbolAddress((void**)&pA2, g_attn2);
    cudaGetSymbolAddress((void**)&pFF, g_ff);
    cudaGetSymbolAddress((void**)&pTmp, g_tmp);

    // K/V projections + area pooling: shared by both attention passes
    tgemm_k<false, 1, false><<<dim3(HD / 128, ROWS / 128, 1), 256>>>(
        hidden, Wk, bk, pK, ROWS, HD, HIDN, 1.f, 0, 0, 0);
    tgemm_k<false, 1, false><<<dim3(HD / 128, ROWS / 128, 1), 256>>>(
        hidden, Wv, bv, pV, ROWS, HD, HIDN, 1.f, 0, 0, 0);
    area_pool_k<<<dim3(MPAD, BHCNT), 256>>>(pK, pV, pKa, pVa);

    // attn1 = LN(mha(hidden) + hidden)
    run_attention(hidden, Wq, bq, Wo, bo, pQ, pKa, pVa, pP, pConcat, pTmp);
    resid_ln_k<<<ROWS, 256>>>(pTmp, hidden, pA1);

    // attn2 = LN(attn1 + mha(attn1; K,V from hidden))
    run_attention(pA1, Wq, bq, Wo, bo, pQ, pKa, pVa, pP, pConcat, pTmp);
    resid_ln_k<<<ROWS, 256>>>(pA1, pTmp, pA2);

    // FFN + final LN
    tgemm_k<false, 0, true><<<dim3(FFD / 128, ROWS / 128, 1), 256>>>(
        pA2, W1, b1, pFF, ROWS, FFD, HIDN, 1.f, 0, 0, 0);
    tgemm_k<false, 0, false><<<dim3(HIDN / 128, ROWS / 128, 1), 256>>>(
        pFF, W2, b2, pTmp, ROWS, HIDN, FFD, 1.f, 0, 0, 0);
    resid_ln_k<<<ROWS, 256>>>(pA2, pTmp, out);
}

// round 4
// speedup vs baseline: 7.4993x; 1.2995x over previous
#include <cuda_runtime.h>
#include <math.h>

#define BB    64
#define LL    200
#define LPAD  208      // L padded to mult of 16 (PV GEMM K-dim)
#define HIDN  256
#define NH    8
#define DHD   256
#define HD    2048
#define MAREA 990      // 200+199+198+197+196
#define MPAD  992      // padded memory axis (mult of 16)
#define FFD   1024
#define ROWS  (BB*LL)  // 12800
#define BHCNT (BB*NH)  // 512

// ---------------- scratch (static device globals; no allocation) ----------------
__device__ float g_Q[(size_t)BHCNT*LL*DHD];         // [B,H,L,D]
__device__ float g_K[(size_t)BHCNT*LL*DHD];         // [B,H,L,D]
__device__ float g_V[(size_t)BHCNT*LPAD*DHD];       // [B,H,Lpad,D], rows >=200 zeroed
__device__ float g_Karea[(size_t)BHCNT*MPAD*DHD];   // [B,H,Mpad,D], rows >=990 zeroed
__device__ float g_P[(size_t)BHCNT*LL*MPAD];        // raw logits [B,H,L,Mpad]
__device__ float g_Pt[(size_t)BHCNT*LL*LPAD];       // collapsed probs [B,H,L,Lpad]
__device__ float g_concat[(size_t)ROWS*HD];         // [B,L,HD]
__device__ float g_attn1[(size_t)ROWS*HIDN];
__device__ float g_attn2[(size_t)ROWS*HIDN];
__device__ float g_ff[(size_t)ROWS*FFD];
__device__ float g_tmp[(size_t)ROWS*HIDN];

// ---------------- helpers ----------------
__device__ __forceinline__ unsigned f2tf(float f) {
    unsigned u;
    asm("cvt.rna.tf32.f32 %0, %1;" : "=r"(u) : "f"(f));
    return u;
}

__device__ __forceinline__ void mma_tf32(float* c, const unsigned* a, const unsigned* b) {
    asm volatile(
        "mma.sync.aligned.m16n8k8.row.col.f32.tf32.tf32.f32 "
        "{%0,%1,%2,%3}, {%4,%5,%6,%7}, {%8,%9}, {%0,%1,%2,%3};"
        : "+f"(c[0]), "+f"(c[1]), "+f"(c[2]), "+f"(c[3])
        : "r"(a[0]), "r"(a[1]), "r"(a[2]), "r"(a[3]), "r"(b[0]), "r"(b[1]));
}

// ---------------- 256x128x16 tf32 tensor-core GEMM, 64x64 warp tile ----------------
// C[z] = scale * A[z] @ B[z](^T) + bias, optional relu, output-layout modes.
// MODE 0: C[z*sC + r*Nr + c]
// MODE 1: rows are b*L+l, cols h*256+d -> C[((b*NH+h)*lstride+l)*DHD+d]  (QKV split)
// MODE 2: z = b*NH+h, C[(b*LL+r)*HD + h*DHD + c]                         (head concat)
// Requirements: Kr % 16 == 0, Nr % 8 == 0, 16-byte aligned base pointers.
#define ASTR 264   // A smem row stride in words (256+8 skew -> conflict-free frags)
#define BSTR 136   // B smem row stride in words (128+8 skew)
template<bool TRANSB, int MODE, bool RELU>
__global__ __launch_bounds__(256, 1) void tgemm_k(
    const float* __restrict__ A, const float* __restrict__ Bm,
    const float* __restrict__ bias, float* __restrict__ C,
    int Mr, int Nr, int Kr, float scale,
    size_t sA, size_t sB, size_t sC, int lstride)
{
    __shared__ unsigned As[16 * ASTR];
    __shared__ unsigned Bs[16 * BSTR];

    const int z = blockIdx.z;
    A  += (size_t)z * sA;
    Bm += (size_t)z * sB;

    const int row0 = blockIdx.y * 256;
    const int col0 = blockIdx.x * 128;
    const int tid  = threadIdx.x;
    const int lane = tid & 31;
    const int warp = tid >> 5;
    const int wm = (warp & 3) * 64;   // warp tile: 64 rows x 64 cols
    const int wn = (warp >> 2) * 64;
    const int p  = lane >> 2;
    const int q  = lane & 3;

    // ---- gmem load indexing ----
    const int am = tid;               // A row in tile (0..255), 16 k-words per thread
    int bK, bN;
    if (!TRANSB) { bK = tid >> 4; bN = (tid & 15) * 8; }   // B[k][n]: 2 float4 along n
    else         { bN = tid & 127; bK = (tid >> 7) * 8; }  // B[n][k]: 2 float4 along k

    float4 pa[4], pb[2];
    const float4 Z4 = make_float4(0.f, 0.f, 0.f, 0.f);

    auto loadA = [&](int k0) {
        int gr = row0 + am;
        if (gr < Mr) {
            const float* ap = &A[(size_t)gr * Kr + k0];
#pragma unroll
            for (int i = 0; i < 4; i++) pa[i] = *(const float4*)(ap + 4 * i);
        } else {
#pragma unroll
            for (int i = 0; i < 4; i++) pa[i] = Z4;
        }
    };
    auto loadB = [&](int k0) {
        int gn = col0 + bN;
        if (!TRANSB) {
            if (gn < Nr) {
                pb[0] = *(const float4*)&Bm[(size_t)(k0 + bK) * Nr + gn];
                pb[1] = *(const float4*)&Bm[(size_t)(k0 + bK) * Nr + gn + 4];
            } else { pb[0] = Z4; pb[1] = Z4; }
        } else {
            if (gn < Nr) {
                const float* bp = &Bm[(size_t)gn * Kr + k0 + bK];
                pb[0] = *(const float4*)bp;
                pb[1] = *(const float4*)(bp + 4);
            } else { pb[0] = Z4; pb[1] = Z4; }
        }
    };

    float acc[4][8][4];
#pragma unroll
    for (int i = 0; i < 4; i++)
#pragma unroll
        for (int j = 0; j < 8; j++)
#pragma unroll
            for (int u = 0; u < 4; u++) acc[i][j][u] = 0.f;

    loadA(0);
    loadB(0);

    for (int k0 = 0; k0 < Kr; k0 += 16) {
        __syncthreads();
        // commit prefetched tile to smem as tf32 words
        {
            const float* aw = (const float*)pa;
#pragma unroll
            for (int i = 0; i < 16; i++) As[i * ASTR + am] = f2tf(aw[i]);
            if (!TRANSB) {
                uint4 u0 = make_uint4(f2tf(pb[0].x), f2tf(pb[0].y), f2tf(pb[0].z), f2tf(pb[0].w));
                uint4 u1 = make_uint4(f2tf(pb[1].x), f2tf(pb[1].y), f2tf(pb[1].z), f2tf(pb[1].w));
                *(uint4*)&Bs[bK * BSTR + bN]     = u0;
                *(uint4*)&Bs[bK * BSTR + bN + 4] = u1;
            } else {
                const float* bw = (const float*)pb;
#pragma unroll
                for (int i = 0; i < 8; i++) Bs[(bK + i) * BSTR + bN] = f2tf(bw[i]);
            }
        }
        __syncthreads();

        if (k0 + 16 < Kr) { loadA(k0 + 16); loadB(k0 + 16); }

#pragma unroll
        for (int ks = 0; ks < 2; ks++) {
            const int kb = ks * 8;
            unsigned af[4][4];
#pragma unroll
            for (int im = 0; im < 4; im++) {
                int r = wm + im * 16 + p;
                af[im][0] = As[(kb + q) * ASTR + r];
                af[im][1] = As[(kb + q) * ASTR + r + 8];
                af[im][2] = As[(kb + q + 4) * ASTR + r];
                af[im][3] = As[(kb + q + 4) * ASTR + r + 8];
            }
            unsigned bf[8][2];
#pragma unroll
            for (int in = 0; in < 8; in++) {
                int cn = wn + in * 8 + p;
                bf[in][0] = Bs[(kb + q) * BSTR + cn];
                bf[in][1] = Bs[(kb + q + 4) * BSTR + cn];
            }
#pragma unroll
            for (int im = 0; im < 4; im++)
#pragma unroll
                for (int in = 0; in < 8; in++)
                    mma_tf32(acc[im][in], af[im], bf[in]);
        }
    }

    // ---- epilogue: float2 stores with layout remap ----
#pragma unroll
    for (int im = 0; im < 4; im++) {
#pragma unroll
        for (int half = 0; half < 2; half++) {
            int gr = row0 + wm + im * 16 + p + half * 8;
            if (gr >= Mr) continue;
#pragma unroll
            for (int in = 0; in < 8; in++) {
                int gc = col0 + wn + in * 8 + 2 * q;
                if (gc >= Nr) continue;
                float2 v;
                v.x = acc[im][in][half * 2 + 0] * scale;
                v.y = acc[im][in][half * 2 + 1] * scale;
                if (bias) {
                    float2 bb = *(const float2*)&bias[gc];
                    v.x += bb.x; v.y += bb.y;
                }
                if (RELU) { v.x = fmaxf(v.x, 0.f); v.y = fmaxf(v.y, 0.f); }
                size_t o;
                if (MODE == 0) {
                    o = (size_t)z * sC + (size_t)gr * Nr + gc;
                } else if (MODE == 1) {
                    int b = gr / LL, l = gr - (gr / LL) * LL;
                    int h = gc >> 8, d = gc & 255;
                    o = (((size_t)b * NH + h) * lstride + l) * DHD + d;
                } else {
                    int b = z >> 3, h = z & 7;
                    o = ((size_t)(b * LL + gr)) * HD + (size_t)h * DHD + gc;
                }
                *(float2*)&C[o] = v;
            }
        }
    }
}

// ---------------- area pooling: K max-pool over widths 1..5 ----------------
__global__ void area_pool_k(const float* __restrict__ K, float* __restrict__ Ka)
{
    int d  = threadIdx.x;   // 256
    int m  = blockIdx.x;    // MPAD
    int bh = blockIdx.y;    // 512
    size_t oidx = ((size_t)bh * MPAD + m) * DHD + d;
    if (m >= MAREA) { Ka[oidx] = 0.f; return; }
    int w = 1, rem = m, span = LL;
    while (rem >= span) { rem -= span; span--; w++; }
    int start = rem;
    const float* kp = K + ((size_t)bh * LL + start) * DHD + d;
    float mx = kp[0];
    for (int j = 1; j < w; j++) mx = fmaxf(mx, kp[(size_t)j * DHD]);
    Ka[oidx] = mx;
}

// ---------------- zero V pad rows (deterministic each launch) ----------------
__global__ void zero_vpad_k(float* __restrict__ V)
{
    int bh = blockIdx.x;
    int t  = threadIdx.x;
    for (int r = LL; r < LPAD; r++)
        V[((size_t)bh * LPAD + r) * DHD + t] = 0.f;
}

// ---------------- fused softmax (over M=990) + window-collapse to Pt[L=208] ----------------
// Pt[q][l] = sum over areas (w,start) with start<=l<=start+w-1 of softmax(P)[q][area]
__global__ void softcol_k(const float* __restrict__ P, float* __restrict__ Pt)
{
    __shared__ float sm[MPAD];
    __shared__ float sred[8];
    int x  = blockIdx.x;   // query position 0..199
    int bh = blockIdx.y;
    const float* p = P + ((size_t)bh * LL + x) * MPAD;
    int t = threadIdx.x;

    float vals[4];
    float mx = -1e30f;
#pragma unroll
    for (int i = 0; i < 4; i++) {
        int idx = t + i * 256;
        vals[i] = (idx < MAREA) ? p[idx] : -1e30f;
        mx = fmaxf(mx, vals[i]);
    }
#pragma unroll
    for (int o = 16; o > 0; o >>= 1) mx = fmaxf(mx, __shfl_xor_sync(0xffffffffu, mx, o));
    if ((t & 31) == 0) sred[t >> 5] = mx;
    __syncthreads();
    if (t < 32) {
        float v = (t < 8) ? sred[t] : -1e30f;
#pragma unroll
        for (int o = 4; o > 0; o >>= 1) v = fmaxf(v, __shfl_xor_sync(0xffffffffu, v, o));
        if (t == 0) sred[0] = v;
    }
    __syncthreads();
    float bm = sred[0];
    __syncthreads();
    float s = 0.f;
#pragma unroll
    for (int i = 0; i < 4; i++) {
        int idx = t + i * 256;
        vals[i] = (idx < MAREA) ? __expf(vals[i] - bm) : 0.f;
        s += vals[i];
    }
#pragma unroll
    for (int o = 16; o > 0; o >>= 1) s += __shfl_xor_sync(0xffffffffu, s, o);
    if ((t & 31) == 0) sred[t >> 5] = s;
    __syncthreads();
    if (t < 32) {
        float v = (t < 8) ? sred[t] : 0.f;
#pragma unroll
        for (int o = 4; o > 0; o >>= 1) v += __shfl_xor_sync(0xffffffffu, v, o);
        if (t == 0) sred[0] = v;
    }
    __syncthreads();
    float inv = 1.f / sred[0];
#pragma unroll
    for (int i = 0; i < 4; i++) {
        int idx = t + i * 256;
        if (idx < MPAD) sm[idx] = vals[i] * inv;
    }
    __syncthreads();

    if (t < LPAD) {
        float a = 0.f;
        if (t < LL) {
            int l = t;
            a = sm[l];  // w = 1, start = l
#pragma unroll
            for (int w = 2; w <= 5; w++) {
                const int off = (w == 2) ? 200 : (w == 3) ? 399 : (w == 4) ? 597 : 794;
                int lo = l - w + 1; if (lo < 0) lo = 0;
                int hi = l;         if (hi > LL - w) hi = LL - w;
                for (int st = lo; st <= hi; st++) a += sm[off + st];
            }
        }
        Pt[((size_t)bh * LL + x) * LPAD + t] = a;
    }
}

// ---------------- fused residual add + layernorm (row = 256 = blockDim) ----------------
__global__ void resid_ln_k(const float* __restrict__ a, const float* __restrict__ b,
                           float* __restrict__ o)
{
    int row = blockIdx.x;
    int t   = threadIdx.x;
    size_t idx = (size_t)row * HIDN + t;
    float x = a[idx] + b[idx];
    float s = x, ss = x * x;
    __shared__ float s1[8], s2[8];
#pragma unroll
    for (int off = 16; off > 0; off >>= 1) {
        s  += __shfl_xor_sync(0xffffffffu, s, off);
        ss += __shfl_xor_sync(0xffffffffu, ss, off);
    }
    if ((t & 31) == 0) { s1[t >> 5] = s; s2[t >> 5] = ss; }
    __syncthreads();
    if (t < 32) {
        float u  = (t < 8) ? s1[t] : 0.f;
        float uu = (t < 8) ? s2[t] : 0.f;
#pragma unroll
        for (int off = 4; off > 0; off >>= 1) {
            u  += __shfl_xor_sync(0xffffffffu, u, off);
            uu += __shfl_xor_sync(0xffffffffu, uu, off);
        }
        if (t == 0) { s1[0] = u; s2[0] = uu; }
    }
    __syncthreads();
    float mean = s1[0] * (1.f / HIDN);
    float var  = s2[0] * (1.f / HIDN) - mean * mean;
    o[idx] = (x - mean) * rsqrtf(var + 1e-5f);
}

// ---------------- host orchestration ----------------
static inline int cdiv(int a, int b) { return (a + b - 1) / b; }

static void run_attention(const float* qsrc, const float* Wq, const float* bq,
                          const float* Wo, const float* bo,
                          float* pQ, float* pKa, float* pV, float* pP, float* pPt,
                          float* pConcat, float* pOut)
{
    // Q projection + head split: [12800,256] @ [256,2048]
    tgemm_k<false, 1, false><<<dim3(HD / 128, ROWS / 256, 1), 256>>>(
        qsrc, Wq, bq, pQ, ROWS, HD, HIDN, 1.f, 0, 0, 0, LL);
    // logits = Q @ Karea^T * 1/16, batched over 512 (b,h)
    tgemm_k<true, 0, false><<<dim3(MPAD / 128 + (MPAD % 128 != 0), 1, BHCNT), 256>>>(
        pQ, pKa, nullptr, pP, LL, MPAD, DHD, 0.0625f,
        (size_t)LL * DHD, (size_t)MPAD * DHD, (size_t)LL * MPAD, 0);
    // fused softmax + window collapse: P[*,990] -> Pt[*,208]
    softcol_k<<<dim3(LL, BHCNT), 256>>>(pP, pPt);
    // out = Pt @ V (K=208), concat heads -> [B,L,HD]
    tgemm_k<false, 2, false><<<dim3(DHD / 128, 1, BHCNT), 256>>>(
        pPt, pV, nullptr, pConcat, LL, DHD, LPAD, 1.f,
        (size_t)LL * LPAD, (size_t)LPAD * DHD, 0, 0);
    // output projection: [12800,2048] @ [2048,256]
    tgemm_k<false, 0, false><<<dim3(HIDN / 128, ROWS / 256, 1), 256>>>(
        pConcat, Wo, bo, pOut, ROWS, HIDN, HD, 1.f, 0, 0, 0, 0);
}

extern "C" void kernel_launch(void* const* d_in, const int* in_sizes, int n_in,
                              void* d_out, int out_size)
{
    const float* hidden = (const float*)d_in[1];
    const float* Wq = (const float*)d_in[2];
    const float* bq = (const float*)d_in[3];
    const float* Wk = (const float*)d_in[4];
    const float* bk = (const float*)d_in[5];
    const float* Wv = (const float*)d_in[6];
    const float* bv = (const float*)d_in[7];
    const float* Wo = (const float*)d_in[8];
    const float* bo = (const float*)d_in[9];
    const float* W1 = (const float*)d_in[10];
    const float* b1 = (const float*)d_in[11];
    const float* W2 = (const float*)d_in[12];
    const float* b2 = (const float*)d_in[13];
    float* out = (float*)d_out;

    float *pQ, *pK, *pV, *pKa, *pP, *pPt, *pConcat, *pA1, *pA2, *pFF, *pTmp;
    cudaGetSymbolAddress((void**)&pQ, g_Q);
    cudaGetSymbolAddress((void**)&pK, g_K);
    cudaGetSymbolAddress((void**)&pV, g_V);
    cudaGetSymbolAddress((void**)&pKa, g_Karea);
    cudaGetSymbolAddress((void**)&pP, g_P);
    cudaGetSymbolAddress((void**)&pPt, g_Pt);
    cudaGetSymbolAddress((void**)&pConcat, g_concat);
    cudaGetSymbolAddress((void**)&pA1, g_attn1);
    cudaGetSymbolAddress((void**)&pA2, g_attn2);
    cudaGetSymbolAddress((void**)&pFF, g_ff);
    cudaGetSymbolAddress((void**)&pTmp, g_tmp);

    // K/V projections + K area pooling: shared by both attention passes
    tgemm_k<false, 1, false><<<dim3(HD / 128, ROWS / 256, 1), 256>>>(
        hidden, Wk, bk, pK, ROWS, HD, HIDN, 1.f, 0, 0, 0, LL);
    tgemm_k<false, 1, false><<<dim3(HD / 128, ROWS / 256, 1), 256>>>(
        hidden, Wv, bv, pV, ROWS, HD, HIDN, 1.f, 0, 0, 0, LPAD);
    zero_vpad_k<<<BHCNT, 256>>>(pV);
    area_pool_k<<<dim3(MPAD, BHCNT), 256>>>(pK, pKa);

    // attn1 = LN(mha(hidden) + hidden)
    run_attention(hidden, Wq, bq, Wo, bo, pQ, pKa, pV, pP, pPt, pConcat, pTmp);
    resid_ln_k<<<ROWS, 256>>>(pTmp, hidden, pA1);

    // attn2 = LN(attn1 + mha(attn1; K,V from hidden))
    run_attention(pA1, Wq, bq, Wo, bo, pQ, pKa, pV, pP, pPt, pConcat, pTmp);
    resid_ln_k<<<ROWS, 256>>>(pA1, pTmp, pA2);

    // FFN + final LN
    tgemm_k<false, 0, true><<<dim3(FFD / 128, ROWS / 256, 1), 256>>>(
        pA2, W1, b1, pFF, ROWS, FFD, HIDN, 1.f, 0, 0, 0, 0);
    tgemm_k<false, 0, false><<<dim3(HIDN / 128, ROWS / 256, 1), 256>>>(
        pFF, W2, b2, pTmp, ROWS, HIDN, FFD, 1.f, 0, 0, 0, 0);
    resid_ln_k<<<ROWS, 256>>>(pA2, pTmp, out);
}